// round 13
// baseline (speedup 1.0000x reference)
#include <cuda_runtime.h>
#include <cuda_fp16.h>
#include <cstdint>

#define D        128
#define TM       32              // rows per CTA (4 CTAs co-resident per SM)
#define NTH      128
#define TSTEPS   100

#define PADB     272             // bytes per fp16 tile row (136 h, ≡4 words mod 32)
#define TILE_A   (TM * PADB)     // 8704
#define TILE_B   (D * PADB)      // 34816

// ---- dynamic smem byte offsets (~55KB per CTA -> 4 CTAs/SM) ----
#define OFF_C1H   0                      // C1 as half2: [kp=64][r=32], 8KB
#define OFF_A     8192                   // h1 fp16 tile [m][k]
#define OFF_B     (OFF_A + TILE_A)       // W2^T fp16 tile [n][k]
#define OFF_SMALL (OFF_B + TILE_B)       // 51712

struct Small {
    float w1x[D], w1t[D], b1s[D];
    float tembs[TSTEPS];
    float predp[4][TM];
    float b3v;
};

__device__ __forceinline__ uint32_t smem_u32(const void* p) {
    uint32_t a;
    asm("{ .reg .u64 t; cvta.to.shared.u64 t, %1; cvt.u32.u64 %0, t; }" : "=r"(a) : "l"(p));
    return a;
}
// packed silu: x*sigmoid(x) = 0.5x + 0.5x*tanh(x/2); ONE MUFU for TWO values
__device__ __forceinline__ __half2 silu_h2(__half2 v) {
    __half2 hv = __hmul2(v, __float2half2_rn(0.5f));
    uint32_t ui = *(uint32_t*)&hv, uo;
    asm("tanh.approx.f16x2 %0, %1;" : "=r"(uo) : "r"(ui));
    __half2 th = *(__half2*)&uo;
    return __hfma2(hv, th, hv);
}
__device__ __forceinline__ void ldm4(uint32_t* r, uint32_t addr) {
    asm volatile("ldmatrix.sync.aligned.m8n8.x4.shared.b16 {%0,%1,%2,%3}, [%4];"
                 : "=r"(r[0]), "=r"(r[1]), "=r"(r[2]), "=r"(r[3]) : "r"(addr));
}
__device__ __forceinline__ void mma16816(float* c, const uint32_t* a, const uint32_t* b) {
    asm volatile(
        "mma.sync.aligned.m16n8k16.row.col.f32.f16.f16.f32 "
        "{%0,%1,%2,%3}, {%4,%5,%6,%7}, {%8,%9}, {%0,%1,%2,%3};"
        : "+f"(c[0]), "+f"(c[1]), "+f"(c[2]), "+f"(c[3])
        : "r"(a[0]), "r"(a[1]), "r"(a[2]), "r"(a[3]), "r"(b[0]), "r"(b[1]));
}

extern "C" __global__ void __launch_bounds__(NTH, 4)
diff_kernel(const float* __restrict__ gctx,
            const float* __restrict__ gx0,
            const float* __restrict__ gnoise,
            const float* __restrict__ gW1,
            const float* __restrict__ gb1,
            const float* __restrict__ gW2,
            const float* __restrict__ gb2,
            const float* __restrict__ gW3,
            const float* __restrict__ gb3,
            const float* __restrict__ gtemb,
            float* __restrict__ gout,
            int B)
{
    extern __shared__ char smb[];
    __half2* C1h = (__half2*)(smb + OFF_C1H);   // [kp][r]
    Small*   S   = (Small*)(smb + OFF_SMALL);

    const int tid = threadIdx.x;
    const int w   = tid >> 5;
    const int l   = tid & 31;
    const int rowBase = blockIdx.x * TM;

    // ---- scalars + ctx^T staging (fp32 scratch in A/B region) ----
    float* ctxT = (float*)(smb + OFF_A);        // [d][r] 128x32 fp32 = 16KB
    S->w1x[tid] = gW1[D * D + tid];
    S->w1t[tid] = gW1[D * D + D + tid];
    S->b1s[tid] = gb1[tid];
    if (tid < TSTEPS) S->tembs[tid] = gtemb[tid];
    if (tid == 0)     S->b3v = gb3[0];
    // per-thread x state (row l), redundant across warps
    float xr = gx0[rowBase + l];

    for (int i = tid; i < D * TM / 4; i += NTH) {
        int r  = i >> 5;                 // 0..31
        int d4 = (i & 31) << 2;          // 0,4,..,124
        float4 v = *(const float4*)&gctx[(size_t)(rowBase + r) * D + d4];
        ctxT[(d4 + 0) * TM + r] = v.x;
        ctxT[(d4 + 1) * TM + r] = v.y;
        ctxT[(d4 + 2) * TM + r] = v.z;
        ctxT[(d4 + 3) * TM + r] = v.w;
    }
    __syncthreads();

    // ---- prologue GEMM (once): acc = ctx@W1; W1 via L2 ----
    {
        const int j0 = (tid & 15) * 8;
        const int r0 = (tid >> 4) * 4;
        float pacc[4][8];
#pragma unroll
        for (int a = 0; a < 4; ++a)
#pragma unroll
            for (int b = 0; b < 8; ++b) pacc[a][b] = 0.0f;
#pragma unroll 4
        for (int d = 0; d < D; ++d) {
            float4 av4 = *(const float4*)&ctxT[d * TM + r0];
            float4 w0  = *(const float4*)&gW1[d * D + j0];
            float4 w1  = *(const float4*)&gW1[d * D + j0 + 4];
            float av[4] = {av4.x, av4.y, av4.z, av4.w};
            float bv[8] = {w0.x, w0.y, w0.z, w0.w, w1.x, w1.y, w1.z, w1.w};
#pragma unroll
            for (int a = 0; a < 4; ++a)
#pragma unroll
                for (int b = 0; b < 8; ++b)
                    pacc[a][b] = fmaf(av[a], bv[b], pacc[a][b]);
        }
        __syncthreads();                 // ctxT reads done; scratch reusable

        // store C1 as half2 k-pairs: C1h[kp][r]
#pragma unroll
        for (int p = 0; p < 4; ++p) {
            int j  = j0 + 2 * p;
            int kp = j >> 1;
            float bz0 = S->b1s[j], bz1 = S->b1s[j + 1];
#pragma unroll
            for (int a = 0; a < 4; ++a)
                C1h[kp * TM + r0 + a] =
                    __floats2half2_rn(pacc[a][2 * p] + bz0, pacc[a][2 * p + 1] + bz1);
        }
    }

    // ---- build B tile once: Bt[n][k] = W2[k][n] fp16, stride 272B ----
    for (int idx = tid; idx < D * D; idx += NTH) {
        int k = idx >> 7, n = idx & 127;
        *(__half*)(smb + OFF_B + n * PADB + k * 2) = __float2half_rn(gW2[idx]);
    }

    // running cumprod: start at acp_99, divide down each step
    float acp = 1.0f;
#pragma unroll 4
    for (int t = 0; t < TSTEPS; ++t)
        acp *= 1.0f - (1e-4f + (0.02f - 1e-4f) * ((float)t * (1.0f / 99.0f)));
    __syncthreads();

    // ---- per-thread roles ----
    const int khp = w << 4;                  // phase-1 k-pair base: 0,16,32,48
    const int rot = l >> 3;
    char* At = smb + OFF_A;

    const int nq = w;                        // phase-2: warp covers cols [32w, 32w+32)
    const uint32_t aBase = smem_u32(smb + OFF_A)
                         + (uint32_t)(l & 15) * PADB + (uint32_t)(l >> 4) * 16;
    const uint32_t bBase = smem_u32(smb + OFF_B)
                         + (uint32_t)(nq * 32 + (l & 15)) * PADB + (uint32_t)(l >> 4) * 16;

    // ---- persist B fragments for kc=0..3 (32 regs); kc=4..7 streamed ----
    uint32_t Bf[4][4][2];
#pragma unroll
    for (int kc = 0; kc < 4; ++kc)
#pragma unroll
        for (int nb = 0; nb < 2; ++nb) {
            uint32_t q[4];
            ldm4(q, bBase + nb * 16 * PADB + kc * 32);
            Bf[kc][2 * nb][0] = q[0];     Bf[kc][2 * nb][1] = q[2];
            Bf[kc][2 * nb + 1][0] = q[1]; Bf[kc][2 * nb + 1][1] = q[3];
        }

    // hoisted epilogue constants (packed half2, from gmem): cols c(n8), c(n8)+1
    __half2 b2h2[4], w3h2[4];
#pragma unroll
    for (int n8 = 0; n8 < 4; ++n8) {
        int c = nq * 32 + n8 * 8 + (l & 3) * 2;
        b2h2[n8] = __floats2half2_rn(gb2[c], gb2[c + 1]);
        w3h2[n8] = __floats2half2_rn(gW3[c], gW3[c + 1]);
    }

    for (int it = 0; it < TSTEPS; ++it) {
        const int t = TSTEPS - 1 - it;
        const float temb  = S->tembs[t];
        const float beta  = 1e-4f + (0.02f - 1e-4f) * ((float)t * (1.0f / 99.0f));
        const float alpha = 1.0f - beta;
        const float cAv   = 1.0f / sqrtf(alpha);
        const float cBv   = beta / sqrtf(1.0f - acp);
        const float cCv   = (t > 0) ? sqrtf(beta) : 0.0f;

        // prefetch this step's noise (per-thread; L1 broadcast across warps)
        const float nz = gnoise[(size_t)it * (size_t)B + rowBase + l];

        // ---- phase 1: pre-act in f32, packed f16x2 silu -> fp16 A tile ----
#pragma unroll 4
        for (int j = 0; j < 16; ++j) {
            int kpg = khp + (j ^ rot);           // k-pair index 0..63
            int k   = kpg * 2;
            float2 c = __half22float2(C1h[kpg * TM + l]);
            float p0 = fmaf(xr, S->w1x[k],     c.x) + temb * S->w1t[k];
            float p1 = fmaf(xr, S->w1x[k + 1], c.y) + temb * S->w1t[k + 1];
            __half2 h = silu_h2(__floats2half2_rn(p0, p1));
            *(__half2*)(At + l * PADB + kpg * 4) = h;
        }
        __syncthreads();

        // ---- phase 2: out = A @ B^T  (fp16 HMMA; B half-persisted) ----
        float acc[2][4][4];
#pragma unroll
        for (int mc = 0; mc < 2; ++mc)
#pragma unroll
            for (int n8 = 0; n8 < 4; ++n8)
#pragma unroll
                for (int q = 0; q < 4; ++q) acc[mc][n8][q] = 0.0f;

        // kc = 0..3: B from registers
#pragma unroll
        for (int kc = 0; kc < 4; ++kc) {
#pragma unroll
            for (int mc = 0; mc < 2; ++mc) {
                uint32_t af[4];
                ldm4(af, aBase + mc * 16 * PADB + kc * 32);
#pragma unroll
                for (int n8 = 0; n8 < 4; ++n8)
                    mma16816(acc[mc][n8], af, Bf[kc][n8]);
            }
        }
        // kc = 4..7: B streamed from smem
#pragma unroll
        for (int kc = 4; kc < 8; ++kc) {
            uint32_t bf[4][2];
#pragma unroll
            for (int nb = 0; nb < 2; ++nb) {
                uint32_t q[4];
                ldm4(q, bBase + nb * 16 * PADB + kc * 32);
                bf[2 * nb][0] = q[0];     bf[2 * nb][1] = q[2];
                bf[2 * nb + 1][0] = q[1]; bf[2 * nb + 1][1] = q[3];
            }
#pragma unroll
            for (int mc = 0; mc < 2; ++mc) {
                uint32_t af[4];
                ldm4(af, aBase + mc * 16 * PADB + kc * 32);
#pragma unroll
                for (int n8 = 0; n8 < 4; ++n8)
                    mma16816(acc[mc][n8], af, bf[n8]);
            }
        }

        // ---- epilogue: packed silu(out+b2)·w3 row-sum; quad shfl reduce ----
        float rs[2][2];
        rs[0][0] = rs[0][1] = rs[1][0] = rs[1][1] = 0.0f;
#pragma unroll
        for (int mc = 0; mc < 2; ++mc)
#pragma unroll
            for (int n8 = 0; n8 < 4; ++n8) {
                __half2 p0 = __hadd2(__floats2half2_rn(acc[mc][n8][0], acc[mc][n8][1]), b2h2[n8]);
                __half2 p1 = __hadd2(__floats2half2_rn(acc[mc][n8][2], acc[mc][n8][3]), b2h2[n8]);
                __half2 s0 = __hmul2(silu_h2(p0), w3h2[n8]);
                __half2 s1 = __hmul2(silu_h2(p1), w3h2[n8]);
                float2 f0 = __half22float2(s0);
                float2 f1 = __half22float2(s1);
                rs[mc][0] += f0.x + f0.y;
                rs[mc][1] += f1.x + f1.y;
            }
#pragma unroll
        for (int s = 1; s < 4; s <<= 1) {
#pragma unroll
            for (int mc = 0; mc < 2; ++mc) {
                rs[mc][0] += __shfl_xor_sync(0xffffffffu, rs[mc][0], s);
                rs[mc][1] += __shfl_xor_sync(0xffffffffu, rs[mc][1], s);
            }
        }
        if ((l & 3) == 0) {
            int rq = l >> 2;
#pragma unroll
            for (int mc = 0; mc < 2; ++mc) {
                S->predp[nq][mc * 16 + rq]     = rs[mc][0];
                S->predp[nq][mc * 16 + 8 + rq] = rs[mc][1];
            }
        }
        __syncthreads();

        // ---- x update (thread-local, redundant across warps) ----
        {
            float p = S->predp[0][l] + S->predp[1][l]
                    + S->predp[2][l] + S->predp[3][l] + S->b3v;
            xr = (xr - cBv * p) * cAv + cCv * nz;
        }
        acp /= alpha;                       // acp_{t-1} for next iteration
    }

    if (tid < 32)
        gout[rowBase + l] = xr;
}

extern "C" void kernel_launch(void* const* d_in, const int* in_sizes, int n_in,
                              void* d_out, int out_size)
{
    const float* ctx = (const float*)d_in[0];
    const float* x0  = (const float*)d_in[1];
    const float* nz  = (const float*)d_in[2];
    const float* W1  = (const float*)d_in[3];
    const float* b1  = (const float*)d_in[4];
    const float* W2  = (const float*)d_in[5];
    const float* b2  = (const float*)d_in[6];
    const float* W3  = (const float*)d_in[7];
    const float* b3  = (const float*)d_in[8];
    const float* te  = (const float*)d_in[9];
    float* out = (float*)d_out;

    const int B = in_sizes[1];
    const size_t smem = OFF_SMALL + sizeof(Small);   // ~53 KB -> 4 CTAs/SM

    cudaFuncSetAttribute(diff_kernel,
                         cudaFuncAttributeMaxDynamicSharedMemorySize,
                         (int)smem);

    diff_kernel<<<B / TM, NTH, smem>>>(ctx, x0, nz, W1, b1, W2, b2, W3, b3, te,
                                       out, B);
}

// round 14
// speedup vs baseline: 1.2767x; 1.2767x over previous
#include <cuda_runtime.h>
#include <cuda_fp16.h>
#include <cstdint>

#define D        128
#define TM       32              // rows per CTA (4 CTAs co-resident per SM)
#define NTH      128
#define TSTEPS   100

#define PADB     272             // bytes per tile row (136 halves, ≡4 words mod 32)
#define TILE_A   (TM * PADB)     // 8704
#define TILE_B   (D * PADB)      // 34816

// ---- dynamic smem byte offsets (~55KB per CTA -> 4 CTAs/SM) ----
#define OFF_C1H   0                      // C1 half2 row-major: [r=32][kp=64], 272B rows
#define OFF_A     8704                   // h1 fp16 tile [m][k]
#define OFF_B     (OFF_A + TILE_A)       // W2^T fp16 tile [n][k]
#define OFF_SMALL (OFF_B + TILE_B)       // 52224

struct Small {
    float w1x[D], w1t[D], b1s[D];
    float tembs[TSTEPS];
    float predp[4][TM];
    float b3v;
};

__device__ __forceinline__ uint32_t smem_u32(const void* p) {
    uint32_t a;
    asm("{ .reg .u64 t; cvta.to.shared.u64 t, %1; cvt.u32.u64 %0, t; }" : "=r"(a) : "l"(p));
    return a;
}
// silu = 0.5x + 0.5x*tanh(x/2): ONE MUFU (f32 — R12 numerics)
__device__ __forceinline__ float silu_f(float v) {
    float th, hv = 0.5f * v;
    asm("tanh.approx.f32 %0, %1;" : "=f"(th) : "f"(hv));
    return fmaf(hv, th, hv);
}
__device__ __forceinline__ void ldm4(uint32_t* r, uint32_t addr) {
    asm volatile("ldmatrix.sync.aligned.m8n8.x4.shared.b16 {%0,%1,%2,%3}, [%4];"
                 : "=r"(r[0]), "=r"(r[1]), "=r"(r[2]), "=r"(r[3]) : "r"(addr));
}
__device__ __forceinline__ void mma16816(float* c, const uint32_t* a, const uint32_t* b) {
    asm volatile(
        "mma.sync.aligned.m16n8k16.row.col.f32.f16.f16.f32 "
        "{%0,%1,%2,%3}, {%4,%5,%6,%7}, {%8,%9}, {%0,%1,%2,%3};"
        : "+f"(c[0]), "+f"(c[1]), "+f"(c[2]), "+f"(c[3])
        : "r"(a[0]), "r"(a[1]), "r"(a[2]), "r"(a[3]), "r"(b[0]), "r"(b[1]));
}

extern "C" __global__ void __launch_bounds__(NTH, 4)
diff_kernel(const float* __restrict__ gctx,
            const float* __restrict__ gx0,
            const float* __restrict__ gnoise,
            const float* __restrict__ gW1,
            const float* __restrict__ gb1,
            const float* __restrict__ gW2,
            const float* __restrict__ gb2,
            const float* __restrict__ gW3,
            const float* __restrict__ gb3,
            const float* __restrict__ gtemb,
            float* __restrict__ gout,
            int B)
{
    extern __shared__ char smb[];
    Small* S = (Small*)(smb + OFF_SMALL);

    const int tid = threadIdx.x;
    const int w   = tid >> 5;
    const int l   = tid & 31;
    const int rowBase = blockIdx.x * TM;

    // ---- scalars + ctx^T staging (fp32 scratch in A/B region) ----
    float* ctxT = (float*)(smb + OFF_A);        // [d][r] 128x32 fp32 = 16KB
    S->w1x[tid] = gW1[D * D + tid];
    S->w1t[tid] = gW1[D * D + D + tid];
    S->b1s[tid] = gb1[tid];
    if (tid < TSTEPS) S->tembs[tid] = gtemb[tid];
    if (tid == 0)     S->b3v = gb3[0];
    // per-thread x state (row l), redundant across warps
    float xr = gx0[rowBase + l];

    for (int i = tid; i < D * TM / 4; i += NTH) {
        int r  = i >> 5;                 // 0..31
        int d4 = (i & 31) << 2;          // 0,4,..,124
        float4 v = *(const float4*)&gctx[(size_t)(rowBase + r) * D + d4];
        ctxT[(d4 + 0) * TM + r] = v.x;
        ctxT[(d4 + 1) * TM + r] = v.y;
        ctxT[(d4 + 2) * TM + r] = v.z;
        ctxT[(d4 + 3) * TM + r] = v.w;
    }
    __syncthreads();

    // ---- prologue GEMM (once): acc = ctx@W1; W1 via L2 ----
    {
        const int j0 = (tid & 15) * 8;
        const int r0 = (tid >> 4) * 4;
        float pacc[4][8];
#pragma unroll
        for (int a = 0; a < 4; ++a)
#pragma unroll
            for (int b = 0; b < 8; ++b) pacc[a][b] = 0.0f;
#pragma unroll 4
        for (int d = 0; d < D; ++d) {
            float4 av4 = *(const float4*)&ctxT[d * TM + r0];
            float4 w0  = *(const float4*)&gW1[d * D + j0];
            float4 w1  = *(const float4*)&gW1[d * D + j0 + 4];
            float av[4] = {av4.x, av4.y, av4.z, av4.w};
            float bv[8] = {w0.x, w0.y, w0.z, w0.w, w1.x, w1.y, w1.z, w1.w};
#pragma unroll
            for (int a = 0; a < 4; ++a)
#pragma unroll
                for (int b = 0; b < 8; ++b)
                    pacc[a][b] = fmaf(av[a], bv[b], pacc[a][b]);
        }
        __syncthreads();                 // ctxT reads done; scratch reusable

        // store C1 row-major half2: C1h[r][kp], row stride 272B
#pragma unroll
        for (int p = 0; p < 4; ++p) {
            int j  = j0 + 2 * p;
            int kp = j >> 1;
            float bz0 = S->b1s[j], bz1 = S->b1s[j + 1];
#pragma unroll
            for (int a = 0; a < 4; ++a)
                *(__half2*)(smb + OFF_C1H + (r0 + a) * PADB + kp * 4) =
                    __floats2half2_rn(pacc[a][2 * p] + bz0, pacc[a][2 * p + 1] + bz1);
        }
    }

    // ---- build B tile once: Bt[n][k] = W2[k][n] fp16, stride 272B ----
    for (int idx = tid; idx < D * D; idx += NTH) {
        int k = idx >> 7, n = idx & 127;
        *(__half*)(smb + OFF_B + n * PADB + k * 2) = __float2half_rn(gW2[idx]);
    }

    // running cumprod: start at acp_99, divide down each step
    float acp = 1.0f;
#pragma unroll 4
    for (int t = 0; t < TSTEPS; ++t)
        acp *= 1.0f - (1e-4f + (0.02f - 1e-4f) * ((float)t * (1.0f / 99.0f)));
    __syncthreads();

    // ---- per-thread roles ----
    const int khp = w << 4;                  // phase-1 k-pair base: 0,16,32,48
    char* At  = smb + OFF_A;
    char* C1p = smb + OFF_C1H;

    const int nq = w;                        // phase-2: warp covers cols [32w, 32w+32)
    const uint32_t aBase = smem_u32(smb + OFF_A)
                         + (uint32_t)(l & 15) * PADB + (uint32_t)(l >> 4) * 16;
    const uint32_t bBase = smem_u32(smb + OFF_B)
                         + (uint32_t)(nq * 32 + (l & 15)) * PADB + (uint32_t)(l >> 4) * 16;

    // ---- persist B fragments for kc=0..3 (32 regs); kc=4..7 streamed ----
    uint32_t Bf[4][4][2];
#pragma unroll
    for (int kc = 0; kc < 4; ++kc)
#pragma unroll
        for (int nb = 0; nb < 2; ++nb) {
            uint32_t q[4];
            ldm4(q, bBase + nb * 16 * PADB + kc * 32);
            Bf[kc][2 * nb][0] = q[0];     Bf[kc][2 * nb][1] = q[2];
            Bf[kc][2 * nb + 1][0] = q[1]; Bf[kc][2 * nb + 1][1] = q[3];
        }

    // hoisted epilogue constants (f32, R12 path): cols c(n8) = nq*32+n8*8+(l%4)*2+{0,1}
    float b2v0[4], b2v1[4], w3v0[4], w3v1[4];
#pragma unroll
    for (int n8 = 0; n8 < 4; ++n8) {
        int c = nq * 32 + n8 * 8 + (l & 3) * 2;
        b2v0[n8] = gb2[c];     b2v1[n8] = gb2[c + 1];
        w3v0[n8] = gW3[c];     w3v1[n8] = gW3[c + 1];
    }

    for (int it = 0; it < TSTEPS; ++it) {
        const int t = TSTEPS - 1 - it;
        const float temb  = S->tembs[t];
        const float beta  = 1e-4f + (0.02f - 1e-4f) * ((float)t * (1.0f / 99.0f));
        const float alpha = 1.0f - beta;
        const float cAv   = 1.0f / sqrtf(alpha);
        const float cBv   = beta / sqrtf(1.0f - acp);
        const float cCv   = (t > 0) ? sqrtf(beta) : 0.0f;

        // prefetch this step's noise (per-thread; L1 broadcast across warps)
        const float nz = gnoise[(size_t)it * (size_t)B + rowBase + l];

        // ---- phase 1: vectorized — 4x LDS.128 C1, silu, 4x STS.128 A ----
#pragma unroll
        for (int g = 0; g < 4; ++g) {
            uint4 c4 = *(const uint4*)(C1p + l * PADB + (khp + 4 * g) * 4);
            uint32_t cw[4] = {c4.x, c4.y, c4.z, c4.w};
            uint32_t ow[4];
#pragma unroll
            for (int p = 0; p < 4; ++p) {
                int k = (khp + 4 * g + p) * 2;
                float2 cf = __half22float2(*(__half2*)&cw[p]);
                float h0 = silu_f(fmaf(xr, S->w1x[k],     cf.x) + temb * S->w1t[k]);
                float h1 = silu_f(fmaf(xr, S->w1x[k + 1], cf.y) + temb * S->w1t[k + 1]);
                __half2 hh = __floats2half2_rn(h0, h1);
                ow[p] = *(uint32_t*)&hh;
            }
            *(uint4*)(At + l * PADB + (khp + 4 * g) * 4) =
                make_uint4(ow[0], ow[1], ow[2], ow[3]);
        }
        __syncthreads();

        // ---- phase 2: out = A @ B^T  (fp16 HMMA; B half-persisted) ----
        float acc[2][4][4];
#pragma unroll
        for (int mc = 0; mc < 2; ++mc)
#pragma unroll
            for (int n8 = 0; n8 < 4; ++n8)
#pragma unroll
                for (int q = 0; q < 4; ++q) acc[mc][n8][q] = 0.0f;

        // kc = 0..3: B from registers
#pragma unroll
        for (int kc = 0; kc < 4; ++kc) {
#pragma unroll
            for (int mc = 0; mc < 2; ++mc) {
                uint32_t af[4];
                ldm4(af, aBase + mc * 16 * PADB + kc * 32);
#pragma unroll
                for (int n8 = 0; n8 < 4; ++n8)
                    mma16816(acc[mc][n8], af, Bf[kc][n8]);
            }
        }
        // kc = 4..7: B streamed from smem
#pragma unroll
        for (int kc = 4; kc < 8; ++kc) {
            uint32_t bf[4][2];
#pragma unroll
            for (int nb = 0; nb < 2; ++nb) {
                uint32_t q[4];
                ldm4(q, bBase + nb * 16 * PADB + kc * 32);
                bf[2 * nb][0] = q[0];     bf[2 * nb][1] = q[2];
                bf[2 * nb + 1][0] = q[1]; bf[2 * nb + 1][1] = q[3];
            }
#pragma unroll
            for (int mc = 0; mc < 2; ++mc) {
                uint32_t af[4];
                ldm4(af, aBase + mc * 16 * PADB + kc * 32);
#pragma unroll
                for (int n8 = 0; n8 < 4; ++n8)
                    mma16816(acc[mc][n8], af, bf[n8]);
            }
        }

        // ---- epilogue (R12 f32 path): silu(out+b2)·w3 row-sum; quad shfl ----
        float rs[2][2];
        rs[0][0] = rs[0][1] = rs[1][0] = rs[1][1] = 0.0f;
#pragma unroll
        for (int mc = 0; mc < 2; ++mc)
#pragma unroll
            for (int n8 = 0; n8 < 4; ++n8) {
                rs[mc][0] = fmaf(silu_f(acc[mc][n8][0] + b2v0[n8]), w3v0[n8], rs[mc][0]);
                rs[mc][0] = fmaf(silu_f(acc[mc][n8][1] + b2v1[n8]), w3v1[n8], rs[mc][0]);
                rs[mc][1] = fmaf(silu_f(acc[mc][n8][2] + b2v0[n8]), w3v0[n8], rs[mc][1]);
                rs[mc][1] = fmaf(silu_f(acc[mc][n8][3] + b2v1[n8]), w3v1[n8], rs[mc][1]);
            }
#pragma unroll
        for (int s = 1; s < 4; s <<= 1) {
#pragma unroll
            for (int mc = 0; mc < 2; ++mc) {
                rs[mc][0] += __shfl_xor_sync(0xffffffffu, rs[mc][0], s);
                rs[mc][1] += __shfl_xor_sync(0xffffffffu, rs[mc][1], s);
            }
        }
        if ((l & 3) == 0) {
            int rq = l >> 2;
#pragma unroll
            for (int mc = 0; mc < 2; ++mc) {
                S->predp[nq][mc * 16 + rq]     = rs[mc][0];
                S->predp[nq][mc * 16 + 8 + rq] = rs[mc][1];
            }
        }
        __syncthreads();

        // ---- x update (thread-local, redundant across warps) ----
        {
            float p = S->predp[0][l] + S->predp[1][l]
                    + S->predp[2][l] + S->predp[3][l] + S->b3v;
            xr = (xr - cBv * p) * cAv + cCv * nz;
        }
        acp /= alpha;                       // acp_{t-1} for next iteration
    }

    if (tid < 32)
        gout[rowBase + l] = xr;
}

extern "C" void kernel_launch(void* const* d_in, const int* in_sizes, int n_in,
                              void* d_out, int out_size)
{
    const float* ctx = (const float*)d_in[0];
    const float* x0  = (const float*)d_in[1];
    const float* nz  = (const float*)d_in[2];
    const float* W1  = (const float*)d_in[3];
    const float* b1  = (const float*)d_in[4];
    const float* W2  = (const float*)d_in[5];
    const float* b2  = (const float*)d_in[6];
    const float* W3  = (const float*)d_in[7];
    const float* b3  = (const float*)d_in[8];
    const float* te  = (const float*)d_in[9];
    float* out = (float*)d_out;

    const int B = in_sizes[1];
    const size_t smem = OFF_SMALL + sizeof(Small);   // ~54.5 KB -> 4 CTAs/SM

    cudaFuncSetAttribute(diff_kernel,
                         cudaFuncAttributeMaxDynamicSharedMemorySize,
                         (int)smem);

    diff_kernel<<<B / TM, NTH, smem>>>(ctx, x0, nz, W1, b1, W2, b2, W3, b3, te,
                                       out, B);
}